// round 6
// baseline (speedup 1.0000x reference)
#include <cuda_runtime.h>
#include <cstdint>

// Shapes fixed by the problem: OBS*FEAT = 1536 floats/candidate, out = 2400 floats.
#define ROW_F4      384   // 1536 floats / 4
#define F4_PER_LANE 12    // 384 / 32 lanes
#define TPB         256
#define WARPS_PB    8
#define NBLOCKS     888   // 6 * 148 SMs

// Per-block best keys: (float_bits(dist) << 32) | candidate_index.
// dist >= 0 so IEEE bits are monotone; low-32 index -> ties pick smaller index
// (matches jnp.argmin first-occurrence). Written unconditionally each launch,
// so no init pass is needed.
__device__ unsigned long long g_keys[NBLOCKS];
__device__ unsigned int       g_count = 0;   // reset to 0 by last block each launch

__global__ __launch_bounds__(TPB)
void nn_fused_kernel(const float* __restrict__ in_pose,
                     const float* __restrict__ train,
                     const float* __restrict__ vels,
                     float* __restrict__ out,
                     int N, int out_elems) {
    const int lane = threadIdx.x & 31;
    const int warp = threadIdx.x >> 5;

    // Query pose resident in registers: 12 x float4 per lane.
    float4 q[F4_PER_LANE];
    const float4* qp = reinterpret_cast<const float4*>(in_pose);
#pragma unroll
    for (int i = 0; i < F4_PER_LANE; i++)
        q[i] = qp[i * 32 + lane];

    unsigned long long best = 0xFFFFFFFFFFFFFFFFULL;

    const int gwarp  = blockIdx.x * WARPS_PB + warp;
    const int stride = gridDim.x * WARPS_PB;

    for (int c = gwarp; c < N; c += stride) {
        const float4* row =
            reinterpret_cast<const float4*>(train) + (size_t)c * ROW_F4;
        float acc = 0.0f;
#pragma unroll
        for (int i = 0; i < F4_PER_LANE; i++) {
            float4 v = row[i * 32 + lane];   // coalesced 512B bursts, MLP=12
            float dx = v.x - q[i].x;
            float dy = v.y - q[i].y;
            float dz = v.z - q[i].z;
            float dw = v.w - q[i].w;
            acc += dx * dx + dy * dy + dz * dz + dw * dw;
        }
#pragma unroll
        for (int off = 16; off; off >>= 1)
            acc += __shfl_xor_sync(0xffffffffu, acc, off);

        unsigned long long key =
            ((unsigned long long)__float_as_uint(acc) << 32) | (unsigned)c;
        best = best < key ? best : key;
    }

    // Block reduce: 8 warp keys -> one slot per block.
    __shared__ unsigned long long sbest[WARPS_PB];
    __shared__ bool isLast;
    __shared__ unsigned bestIdx;

    if (lane == 0) sbest[warp] = best;
    __syncthreads();
    if (warp == 0) {
        unsigned long long b =
            (lane < WARPS_PB) ? sbest[lane] : 0xFFFFFFFFFFFFFFFFULL;
#pragma unroll
        for (int off = 4; off; off >>= 1) {
            unsigned long long o = __shfl_xor_sync(0xffffffffu, b, off);
            b = b < o ? b : o;
        }
        if (lane == 0) g_keys[blockIdx.x] = b;
    }

    // Last-block pattern: fence, count arrivals, final block finishes the job.
    if (threadIdx.x == 0) {
        __threadfence();
        unsigned v = atomicAdd(&g_count, 1u);
        isLast = (v == gridDim.x - 1);
        if (isLast) g_count = 0;   // deterministic reset for graph replay
    }
    __syncthreads();
    if (!isLast) return;

    // Final reduction over NBLOCKS keys (all slots written this launch).
    {
        unsigned long long b = 0xFFFFFFFFFFFFFFFFULL;
        for (int i = threadIdx.x; i < NBLOCKS; i += TPB) {
            unsigned long long k = g_keys[i];
            b = b < k ? b : k;
        }
#pragma unroll
        for (int off = 16; off; off >>= 1) {
            unsigned long long o = __shfl_xor_sync(0xffffffffu, b, off);
            b = b < o ? b : o;
        }
        if (lane == 0) sbest[warp] = b;
        __syncthreads();
        if (warp == 0) {
            unsigned long long bb =
                (lane < WARPS_PB) ? sbest[lane] : 0xFFFFFFFFFFFFFFFFULL;
#pragma unroll
            for (int off = 4; off; off >>= 1) {
                unsigned long long o = __shfl_xor_sync(0xffffffffu, bb, off);
                bb = bb < o ? bb : o;
            }
            if (lane == 0) bestIdx = (unsigned)(bb & 0xFFFFFFFFu);
        }
        __syncthreads();
    }

    // Gather the winning target_vels row (2400 floats = 600 float4).
    const float4* s4 = reinterpret_cast<const float4*>(
        vels + (size_t)bestIdx * (size_t)out_elems);
    float4* d4 = reinterpret_cast<float4*>(out);
    const int n4 = out_elems >> 2;
    for (int i = threadIdx.x; i < n4; i += TPB)
        d4[i] = s4[i];
}

extern "C" void kernel_launch(void* const* d_in, const int* in_sizes, int n_in,
                              void* d_out, int out_size) {
    const float* in_pose     = (const float*)d_in[0];  // [OBS, FEAT] = 1536
    const float* train_poses = (const float*)d_in[1];  // [N, OBS, FEAT]
    const float* target_vels = (const float*)d_in[2];  // [N, PRED, FEAT]

    const int row = in_sizes[0];          // 1536
    const int N   = in_sizes[1] / row;    // 100000

    nn_fused_kernel<<<NBLOCKS, TPB>>>(in_pose, train_poses, target_vels,
                                      (float*)d_out, N, out_size);
}